// round 14
// baseline (speedup 1.0000x reference)
#include <cuda_runtime.h>
#include <cstdint>

#define B_   128
#define P_   168
#define HIDC 32
#define CK   6
#define L_   163          // P - CK + 1
#define HIDR 100
#define HIDS 5
#define SKIP 24
#define PT   6
#define KDIM 4032         // P * 24
#define NDIM 32256        // P * HIDC * CK
#define HW_  24
#define M_   24
#define BCH  4096         // B_ * HIDC
#define GIP  304          // padded gi row

#define BN_     224       // GEMM N tile: 144 CTAs exactly
#define STAGE_F 12672     // (128+224)*36 floats per stage
#define NKT     126       // KDIM / 32

typedef unsigned long long ull;

// ---------------- scratch (device globals; no allocation) ----------------
__device__ float d_c2t[L_ * BCH];          // overlap-added, t-major [t][b][ch]
__device__ float d_gi[B_ * L_ * GIP];      // precomputed input projections
__device__ float d_h1[B_ * HIDR];
__device__ float d_hs[B_ * SKIP * HIDS];

// ---------------- helpers ----------------
__device__ __forceinline__ void mma_tf32(float& c0, float& c1, float& c2, float& c3,
                                         uint32_t a0, uint32_t a1, uint32_t a2, uint32_t a3,
                                         uint32_t b0, uint32_t b1) {
    asm volatile(
        "mma.sync.aligned.m16n8k8.row.col.f32.tf32.tf32.f32 "
        "{%0,%1,%2,%3},{%4,%5,%6,%7},{%8,%9},{%0,%1,%2,%3};"
        : "+f"(c0), "+f"(c1), "+f"(c2), "+f"(c3)
        : "r"(a0), "r"(a1), "r"(a2), "r"(a3), "r"(b0), "r"(b1));
}
__device__ __forceinline__ ull pk2(float lo, float hi) {
    ull r; asm("mov.b64 %0,{%1,%2};" : "=l"(r) : "f"(lo), "f"(hi)); return r;
}
__device__ __forceinline__ void unpk2(ull v, float& lo, float& hi) {
    asm("mov.b64 {%0,%1},%2;" : "=f"(lo), "=f"(hi) : "l"(v));
}
__device__ __forceinline__ ull fma2_(ull a, ull b, ull c) {
    ull d; asm("fma.rn.f32x2 %0,%1,%2,%3;" : "=l"(d) : "l"(a), "l"(b), "l"(c));
    return d;
}
__device__ __forceinline__ float tanh_ap(float x) {
    float y; asm("tanh.approx.f32 %0,%1;" : "=f"(y) : "f"(x)); return y;
}
__device__ __forceinline__ float sigm_a(float x) {
    return 0.5f * tanh_ap(0.5f * x) + 0.5f;
}

// ---------------- k0: zero c2t accumulator ----------------
__global__ void k_zero() {
    int i = blockIdx.x * 256 + threadIdx.x;
    if (i < (L_ * BCH) / 4)
        ((float4*)d_c2t)[i] = make_float4(0.f, 0.f, 0.f, 0.f);
}

// ---------------- k1: GEMM + fused overlap-add ----------------
// c[b,n] = relu(x@W^T + bias); n=(ch,k,p); t=p-k; atomicAdd into c2t[t][b][ch].
// BM=128, BN=224, BK=32; 8 warps (2x4), warp tile 64x56; tf32 m16n8k8.
// 3-stage cp.async ring, ONE barrier per tile, fragment double buffering.
__global__ void __launch_bounds__(256, 1) k_gemm(const float* __restrict__ x,
                                                 const float* __restrict__ W,
                                                 const float* __restrict__ bias) {
    extern __shared__ float sm[];
    const int tid = threadIdx.x;
    const long n0 = (long)blockIdx.x * BN_;
    const int lane = tid & 31, warp = tid >> 5;
    const int wm = warp >> 2, wn = warp & 3;
    uint32_t smbase = (uint32_t)__cvta_generic_to_shared(sm);
    const float* gW = W + n0 * KDIM;

    float acc[4][7][4];
#pragma unroll
    for (int i = 0; i < 4; i++)
#pragma unroll
        for (int jj = 0; jj < 7; jj++)
#pragma unroll
            for (int r = 0; r < 4; r++) acc[i][jj][r] = 0.f;

    auto load_tile = [&](int kt, int s) {
        const float* a = x + kt * 32;
        const float* w = gW + kt * 32;
        uint32_t sb = smbase + s * STAGE_F * 4;
#pragma unroll
        for (int i = 0; i < 4; i++) {
            int c = tid + i * 256;
            int row = c >> 3, kq = c & 7;
            asm volatile("cp.async.ca.shared.global [%0],[%1],16;" ::
                         "r"(sb + (row * 36 + kq * 4) * 4),
                         "l"(a + (long)row * KDIM + kq * 4));
        }
#pragma unroll
        for (int i = 0; i < 7; i++) {
            int c = tid + i * 256;
            int n = c >> 3, kq = c & 7;
            asm volatile("cp.async.ca.shared.global [%0],[%1],16;" ::
                         "r"(sb + (4608 + n * 36 + kq * 4) * 4),
                         "l"(w + (long)n * KDIM + kq * 4));
        }
        asm volatile("cp.async.commit_group;");
    };

    // per-thread fragment base offsets
    const int a_r0 = wm * 64 + (lane >> 2);
    const int a_c0 = lane & 3;
    const int b_n0b = wn * 56 + (lane >> 2);
    const int b_k0 = lane & 3;

    auto loadfrag = [&](const float* As, const float* Ws, int kk,
                        uint32_t af[4][4], uint32_t bf[7][2]) {
#pragma unroll
        for (int mt = 0; mt < 4; ++mt) {
            int r0 = a_r0 + mt * 16;
            int c0 = kk + a_c0;
            af[mt][0] = __float_as_uint(As[r0 * 36 + c0]);
            af[mt][1] = __float_as_uint(As[(r0 + 8) * 36 + c0]);
            af[mt][2] = __float_as_uint(As[r0 * 36 + c0 + 4]);
            af[mt][3] = __float_as_uint(As[(r0 + 8) * 36 + c0 + 4]);
        }
#pragma unroll
        for (int nt = 0; nt < 7; ++nt) {
            int n = b_n0b + nt * 8;
            int k = kk + b_k0;
            bf[nt][0] = __float_as_uint(Ws[n * 36 + k]);
            bf[nt][1] = __float_as_uint(Ws[n * 36 + k + 4]);
        }
    };

    load_tile(0, 0);
    load_tile(1, 1);

    for (int kt = 0; kt < NKT; ++kt) {
        asm volatile("cp.async.wait_group 1;");
        __syncthreads();
        // issue next tile's loads before compute (stage safe: its last
        // readers finished before the barrier above)
        if (kt + 2 < NKT) load_tile(kt + 2, (kt + 2) % 3);
        else asm volatile("cp.async.commit_group;");

        const float* As = sm + (kt % 3) * STAGE_F;
        const float* Ws = As + 4608;

        uint32_t af[2][4][4];
        uint32_t bf[2][7][2];
        loadfrag(As, Ws, 0, af[0], bf[0]);
#pragma unroll
        for (int kki = 0; kki < 4; ++kki) {
            const int cur = kki & 1;
            if (kki < 3) loadfrag(As, Ws, (kki + 1) * 8, af[cur ^ 1], bf[cur ^ 1]);
#pragma unroll
            for (int mt = 0; mt < 4; ++mt)
#pragma unroll
                for (int nt = 0; nt < 7; ++nt)
                    mma_tf32(acc[mt][nt][0], acc[mt][nt][1], acc[mt][nt][2], acc[mt][nt][3],
                             af[cur][mt][0], af[cur][mt][1], af[cur][mt][2], af[cur][mt][3],
                             bf[cur][nt][0], bf[cur][nt][1]);
        }
    }
    __syncthreads();

    // ---- fused epilogue: relu(c + bias) overlap-added into c2t ----
#pragma unroll
    for (int nt = 0; nt < 7; ++nt) {
#pragma unroll
        for (int e = 0; e < 2; ++e) {
            int col = (int)n0 + wn * 56 + nt * 8 + 2 * (lane & 3) + e;
            int ch = col / (CK * P_);                 // /1008
            int rem = col - ch * (CK * P_);
            int k = rem / P_;                          // /168
            int t = rem - k * P_ - k;                  // p - k
            if (t >= 0 && t < L_) {
                float bv = bias[col];
                float* base = d_c2t + t * BCH + ch;
#pragma unroll
                for (int mt = 0; mt < 4; ++mt) {
                    int row = wm * 64 + mt * 16 + (lane >> 2);
                    float v0 = fmaxf(acc[mt][nt][e] + bv, 0.f);
                    float v1 = fmaxf(acc[mt][nt][e + 2] + bv, 0.f);
                    atomicAdd(base + row * HIDC, v0);
                    atomicAdd(base + (row + 8) * HIDC, v1);
                }
            }
        }
    }
}

// ---------------- k2: gi = c2t @ Wih^T + bih on tensor cores ----------------
// One CTA per t. M=128 (b), N=320 (300 padded), K=32, tf32 m16n8k8.
__global__ void __launch_bounds__(256, 1) k_gi(const float* __restrict__ Wih,
                                               const float* __restrict__ bih) {
    extern __shared__ float sm[];           // A 128x36 | B 320x36
    float* Bs = sm + 128 * 36;
    const int t = blockIdx.x;
    const int tid = threadIdx.x;
    const int lane = tid & 31, warp = tid >> 5;
    const int wm = warp >> 2, wn = warp & 3;
    uint32_t smbase = (uint32_t)__cvta_generic_to_shared(sm);

    if (tid < 180) {
        int r = 300 + tid / 9, c = (tid % 9) * 4;
        *(float4*)(Bs + r * 36 + c) = make_float4(0.f, 0.f, 0.f, 0.f);
    }
    {
        const float* a = d_c2t + (size_t)t * BCH;
#pragma unroll
        for (int i = 0; i < 4; i++) {
            int c = tid + i * 256;
            int row = c >> 3, kq = c & 7;
            asm volatile("cp.async.ca.shared.global [%0],[%1],16;" ::
                         "r"(smbase + (uint32_t)(row * 36 + kq * 4) * 4),
                         "l"(a + row * HIDC + kq * 4));
        }
    }
    {
        uint32_t bb = smbase + 128 * 36 * 4;
        for (int c = tid; c < 300 * 8; c += 256) {
            int row = c >> 3, kq = c & 7;
            asm volatile("cp.async.ca.shared.global [%0],[%1],16;" ::
                         "r"(bb + (uint32_t)(row * 36 + kq * 4) * 4),
                         "l"(Wih + row * HIDC + kq * 4));
        }
    }
    asm volatile("cp.async.commit_group;");
    asm volatile("cp.async.wait_group 0;");
    __syncthreads();

    float acc[4][10][4];
#pragma unroll
    for (int i = 0; i < 4; i++)
#pragma unroll
        for (int jj = 0; jj < 10; jj++)
#pragma unroll
            for (int r = 0; r < 4; r++) acc[i][jj][r] = 0.f;

#pragma unroll
    for (int kk = 0; kk < 32; kk += 8) {
        uint32_t af[4][4];
        uint32_t bf[10][2];
#pragma unroll
        for (int mt = 0; mt < 4; ++mt) {
            int r0 = wm * 64 + mt * 16 + (lane >> 2);
            int c0 = kk + (lane & 3);
            af[mt][0] = __float_as_uint(sm[r0 * 36 + c0]);
            af[mt][1] = __float_as_uint(sm[(r0 + 8) * 36 + c0]);
            af[mt][2] = __float_as_uint(sm[r0 * 36 + c0 + 4]);
            af[mt][3] = __float_as_uint(sm[(r0 + 8) * 36 + c0 + 4]);
        }
#pragma unroll
        for (int nt = 0; nt < 10; ++nt) {
            int n = wn * 80 + nt * 8 + (lane >> 2);
            int k = kk + (lane & 3);
            bf[nt][0] = __float_as_uint(Bs[n * 36 + k]);
            bf[nt][1] = __float_as_uint(Bs[n * 36 + k + 4]);
        }
#pragma unroll
        for (int mt = 0; mt < 4; ++mt)
#pragma unroll
            for (int nt = 0; nt < 10; ++nt)
                mma_tf32(acc[mt][nt][0], acc[mt][nt][1], acc[mt][nt][2], acc[mt][nt][3],
                         af[mt][0], af[mt][1], af[mt][2], af[mt][3],
                         bf[nt][0], bf[nt][1]);
    }

#pragma unroll
    for (int nt = 0; nt < 10; ++nt) {
        int j = wn * 80 + nt * 8 + 2 * (lane & 3);
        if (j < 300) {
            float b0 = bih[j], b1 = bih[j + 1];
#pragma unroll
            for (int mt = 0; mt < 4; ++mt) {
                int b = wm * 64 + mt * 16 + (lane >> 2);
                float2 v0 = {acc[mt][nt][0] + b0, acc[mt][nt][1] + b1};
                float2 v1 = {acc[mt][nt][2] + b0, acc[mt][nt][3] + b1};
                *(float2*)(d_gi + ((size_t)b * L_ + t) * GIP + j) = v0;
                *(float2*)(d_gi + ((size_t)(b + 8) * L_ + t) * GIP + j) = v1;
            }
        }
    }
}

// ---------------- k3: GRU1 (blocks 0..127) + skip GRU (blocks 128..143) ----
__global__ void __launch_bounds__(320, 1) k_gru(
    const float* __restrict__ g1Whh, const float* __restrict__ g1bhh,
    const float* __restrict__ gsWih, const float* __restrict__ gsWhh,
    const float* __restrict__ gsbih, const float* __restrict__ gsbhh) {
    __shared__ __align__(16) float h_sh[104];
    __shared__ __align__(16) float s_sh[304];
    __shared__ __align__(16) float gi_sh[2][GIP];
    __shared__ __align__(16) float ws[592];      // skip-GRU weight pool
    const int bid = blockIdx.x;
    const int j = threadIdx.x;

    if (bid < B_) {
        uint32_t gb = (uint32_t)__cvta_generic_to_shared(gi_sh);
        const float* gsrc = d_gi + (size_t)bid * L_ * GIP;

        if (j < 76)
            asm volatile("cp.async.ca.shared.global [%0],[%1],16;" ::
                         "r"(gb + (uint32_t)j * 16), "l"(gsrc + j * 4));
        asm volatile("cp.async.commit_group;");

        ull whh2[50];
        float bhh_j = 0.f;
        if (j < 300) {
            const ulonglong2* pw = (const ulonglong2*)(g1Whh + j * HIDR);
#pragma unroll
            for (int q = 0; q < 25; q++) { ulonglong2 v = pw[q]; whh2[2*q] = v.x; whh2[2*q+1] = v.y; }
            bhh_j = g1bhh[j];
        }
        if (j < 104) h_sh[j] = 0.f;
        float h_reg = 0.f;
        asm volatile("cp.async.wait_group 0;");
        __syncthreads();

        for (int t = 0; t < L_; ++t) {
            if (t + 1 < L_) {
                if (j < 76)
                    asm volatile("cp.async.ca.shared.global [%0],[%1],16;" ::
                                 "r"(gb + (uint32_t)(((t + 1) & 1) * GIP + j * 4) * 4),
                                 "l"(gsrc + (size_t)(t + 1) * GIP + j * 4));
                asm volatile("cp.async.commit_group;");
            }
            if (j < 300) {
                const ulonglong2* h2 = (const ulonglong2*)h_sh;
                ull a0 = pk2(bhh_j, 0.f), a1 = pk2(0.f, 0.f);
                ull a2 = pk2(0.f, 0.f),  a3 = pk2(0.f, 0.f);
#pragma unroll
                for (int q = 0; q < 25; q++) {
                    ulonglong2 hv = h2[q];
                    if (q & 1) {
                        a2 = fma2_(hv.x, whh2[2*q], a2);
                        a3 = fma2_(hv.y, whh2[2*q+1], a3);
                    } else {
                        a0 = fma2_(hv.x, whh2[2*q], a0);
                        a1 = fma2_(hv.y, whh2[2*q+1], a1);
                    }
                }
                float l0, h0, l1, h1, l2, h2f, l3, h3;
                unpk2(a0, l0, h0); unpk2(a1, l1, h1);
                unpk2(a2, l2, h2f); unpk2(a3, l3, h3);
                s_sh[j] = ((l0 + h0) + (l1 + h1)) + ((l2 + h2f) + (l3 + h3));
            }
            if (t + 1 < L_) asm volatile("cp.async.wait_group 1;");
            else            asm volatile("cp.async.wait_group 0;");
            __syncthreads();
            if (j < HIDR) {
                const float* gi = gi_sh[t & 1];
                float r = sigm_a(gi[j] + s_sh[j]);
                float z = sigm_a(gi[j + 100] + s_sh[j + 100]);
                float n = tanh_ap(gi[j + 200] + r * s_sh[j + 200]);
                h_reg = z * (h_reg - n) + n;
                h_sh[j] = h_reg;
            }
            __syncthreads();
        }
        if (j < HIDR) d_h1[bid * HIDR + j] = h_reg;
    } else {
        for (int i = j; i < 480; i += 320) ws[i] = gsWih[i];
        for (int i = j; i < 75; i += 320) ws[480 + i] = gsWhh[i];
        if (j < 15) { ws[555 + j] = gsbih[j]; ws[570 + j] = gsbhh[j]; }
        __syncthreads();
        if (j < 192) {
            int seq = (bid - B_) * 192 + j;        // = b*SKIP + sk
            int b = seq / SKIP, sk = seq % SKIP;
            float h[5] = {0.f, 0.f, 0.f, 0.f, 0.f};
            for (int pt = 0; pt < PT; ++pt) {
                const float4* xp = (const float4*)(d_c2t + (size_t)(L_ - PT * SKIP + pt * SKIP + sk) * BCH + b * HIDC);
                float xv[32];
#pragma unroll
                for (int q = 0; q < 8; ++q) {
                    float4 v = xp[q];
                    xv[4*q] = v.x; xv[4*q+1] = v.y; xv[4*q+2] = v.z; xv[4*q+3] = v.w;
                }
                float gi[15], gh[15];
#pragma unroll
                for (int g2 = 0; g2 < 15; ++g2) {
                    float a = ws[555 + g2];
#pragma unroll
                    for (int i2 = 0; i2 < 32; ++i2) a += xv[i2] * ws[g2 * 32 + i2];
                    gi[g2] = a;
                    float bg = ws[570 + g2];
#pragma unroll
                    for (int i2 = 0; i2 < 5; ++i2) bg += h[i2] * ws[480 + g2 * 5 + i2];
                    gh[g2] = bg;
                }
#pragma unroll
                for (int q = 0; q < 5; ++q) {
                    float r = sigm_a(gi[q] + gh[q]);
                    float z = sigm_a(gi[5 + q] + gh[5 + q]);
                    float n = tanh_ap(gi[10 + q] + r * gh[10 + q]);
                    h[q] = z * (h[q] - n) + n;
                }
            }
#pragma unroll
            for (int q = 0; q < 5; ++q) d_hs[seq * 5 + q] = h[q];
        }
    }
}

// ---------------- k4: final linear + highway + sigmoid; warp per output ----
__global__ void __launch_bounds__(768) k_fin(const float* __restrict__ x,
                      const float* __restrict__ lw, const float* __restrict__ lb,
                      const float* __restrict__ hww, const float* __restrict__ hwb,
                      float* __restrict__ out) {
    int b = blockIdx.x;
    int m = threadIdx.x >> 5, lane = threadIdx.x & 31;
    const float* w = lw + m * (HIDR + SKIP * HIDS);
    float a = 0.f;
#pragma unroll
    for (int q = 0; q < 8; ++q) {
        int i = lane + 32 * q;
        if (i < HIDR) a += w[i] * d_h1[b * HIDR + i];
        else if (i < 220) a += w[i] * d_hs[b * 120 + i - 100];
        else if (i < 244) a += hww[i - 220] * x[b * KDIM + (P_ - HW_ + i - 220) * M_ + m];
    }
#pragma unroll
    for (int off = 16; off > 0; off >>= 1)
        a += __shfl_xor_sync(0xffffffffu, a, off);
    if (lane == 0)
        out[b * M_ + m] = 1.f / (1.f + __expf(-(a + lb[m] + hwb[0])));
}

// ---------------- launch ----------------
extern "C" void kernel_launch(void* const* d_in, const int* in_sizes, int n_in,
                              void* d_out, int out_size) {
    const float* x       = (const float*)d_in[0];
    const float* conv_w  = (const float*)d_in[1];
    const float* conv_b  = (const float*)d_in[2];
    const float* g1Wih   = (const float*)d_in[3];
    const float* g1Whh   = (const float*)d_in[4];
    const float* g1bih   = (const float*)d_in[5];
    const float* g1bhh   = (const float*)d_in[6];
    const float* gsWih   = (const float*)d_in[7];
    const float* gsWhh   = (const float*)d_in[8];
    const float* gsbih   = (const float*)d_in[9];
    const float* gsbhh   = (const float*)d_in[10];
    const float* lin1_w  = (const float*)d_in[11];
    const float* lin1_b  = (const float*)d_in[12];
    const float* hw_w    = (const float*)d_in[13];
    const float* hw_b    = (const float*)d_in[14];
    float* out = (float*)d_out;

    cudaFuncSetAttribute(k_gemm, cudaFuncAttributeMaxDynamicSharedMemorySize, 3 * STAGE_F * 4);
    cudaFuncSetAttribute(k_gi, cudaFuncAttributeMaxDynamicSharedMemorySize, (128 + 320) * 36 * 4);

    k_zero<<<(L_ * BCH / 4 + 255) / 256, 256>>>();
    k_gemm<<<NDIM / BN_, 256, 3 * STAGE_F * 4>>>(x, conv_w, conv_b);
    k_gi<<<L_, 256, (128 + 320) * 36 * 4>>>(g1Wih, g1bih);
    k_gru<<<B_ + 16, 320>>>(g1Whh, g1bhh, gsWih, gsWhh, gsbih, gsbhh);
    k_fin<<<B_, 768>>>(x, lin1_w, lin1_b, hw_w, hw_b, out);
}

// round 16
// speedup vs baseline: 1.0011x; 1.0011x over previous
#include <cuda_runtime.h>
#include <cstdint>

#define B_   128
#define P_   168
#define HIDC 32
#define CK   6
#define L_   163          // P - CK + 1
#define HIDR 100
#define HIDS 5
#define SKIP 24
#define PT   6
#define KDIM 4032         // P * 24
#define NDIM 32256        // P * HIDC * CK
#define HW_  24
#define M_   24
#define BCH  4096         // B_ * HIDC
#define GIP  304          // padded gi row

#define BN_     224       // GEMM N tile: 144 CTAs exactly
#define STAGE_F 12672     // (128+224)*36 floats per stage
#define NKT     126       // KDIM / 32

typedef unsigned long long ull;

// ---------------- scratch (device globals; no allocation) ----------------
__device__ float d_c2t[L_ * BCH];          // overlap-added, t-major [t][b][ch]
__device__ float d_gi[B_ * L_ * GIP];      // precomputed input projections
__device__ float d_h1[B_ * HIDR];
__device__ float d_hs[B_ * SKIP * HIDS];

// ---------------- helpers ----------------
__device__ __forceinline__ void mma_tf32(float& c0, float& c1, float& c2, float& c3,
                                         uint32_t a0, uint32_t a1, uint32_t a2, uint32_t a3,
                                         uint32_t b0, uint32_t b1) {
    asm volatile(
        "mma.sync.aligned.m16n8k8.row.col.f32.tf32.tf32.f32 "
        "{%0,%1,%2,%3},{%4,%5,%6,%7},{%8,%9},{%0,%1,%2,%3};"
        : "+f"(c0), "+f"(c1), "+f"(c2), "+f"(c3)
        : "r"(a0), "r"(a1), "r"(a2), "r"(a3), "r"(b0), "r"(b1));
}
__device__ __forceinline__ ull pk2(float lo, float hi) {
    ull r; asm("mov.b64 %0,{%1,%2};" : "=l"(r) : "f"(lo), "f"(hi)); return r;
}
__device__ __forceinline__ void unpk2(ull v, float& lo, float& hi) {
    asm("mov.b64 {%0,%1},%2;" : "=f"(lo), "=f"(hi) : "l"(v));
}
__device__ __forceinline__ ull fma2_(ull a, ull b, ull c) {
    ull d; asm("fma.rn.f32x2 %0,%1,%2,%3;" : "=l"(d) : "l"(a), "l"(b), "l"(c));
    return d;
}
__device__ __forceinline__ float tanh_ap(float x) {
    float y; asm("tanh.approx.f32 %0,%1;" : "=f"(y) : "f"(x)); return y;
}
__device__ __forceinline__ float sigm_a(float x) {
    return 0.5f * tanh_ap(0.5f * x) + 0.5f;
}

// ---------------- k0: zero c2t accumulator ----------------
__global__ void k_zero() {
    int i = blockIdx.x * 256 + threadIdx.x;
    if (i < (L_ * BCH) / 4)
        ((float4*)d_c2t)[i] = make_float4(0.f, 0.f, 0.f, 0.f);
}

// ---------------- k1: GEMM + fused overlap-add ----------------
// c[b,n] = relu(x@W^T + bias); n=(ch,k,p); t=p-k; atomicAdd into c2t[t][b][ch].
__global__ void __launch_bounds__(256, 1) k_gemm(const float* __restrict__ x,
                                                 const float* __restrict__ W,
                                                 const float* __restrict__ bias) {
    extern __shared__ float sm[];
    const int tid = threadIdx.x;
    const long n0 = (long)blockIdx.x * BN_;
    const int lane = tid & 31, warp = tid >> 5;
    const int wm = warp >> 2, wn = warp & 3;
    uint32_t smbase = (uint32_t)__cvta_generic_to_shared(sm);
    const float* gW = W + n0 * KDIM;

    float acc[4][7][4];
#pragma unroll
    for (int i = 0; i < 4; i++)
#pragma unroll
        for (int jj = 0; jj < 7; jj++)
#pragma unroll
            for (int r = 0; r < 4; r++) acc[i][jj][r] = 0.f;

    auto load_tile = [&](int kt, int s) {
        const float* a = x + kt * 32;
        const float* w = gW + kt * 32;
        uint32_t sb = smbase + s * STAGE_F * 4;
#pragma unroll
        for (int i = 0; i < 4; i++) {
            int c = tid + i * 256;
            int row = c >> 3, kq = c & 7;
            asm volatile("cp.async.ca.shared.global [%0],[%1],16;" ::
                         "r"(sb + (row * 36 + kq * 4) * 4),
                         "l"(a + (long)row * KDIM + kq * 4));
        }
#pragma unroll
        for (int i = 0; i < 7; i++) {
            int c = tid + i * 256;
            int n = c >> 3, kq = c & 7;
            asm volatile("cp.async.ca.shared.global [%0],[%1],16;" ::
                         "r"(sb + (4608 + n * 36 + kq * 4) * 4),
                         "l"(w + (long)n * KDIM + kq * 4));
        }
        asm volatile("cp.async.commit_group;");
    };

    const int a_r0 = wm * 64 + (lane >> 2);
    const int a_c0 = lane & 3;
    const int b_n0b = wn * 56 + (lane >> 2);
    const int b_k0 = lane & 3;

    auto loadfrag = [&](const float* As, const float* Ws, int kk,
                        uint32_t af[4][4], uint32_t bf[7][2]) {
#pragma unroll
        for (int mt = 0; mt < 4; ++mt) {
            int r0 = a_r0 + mt * 16;
            int c0 = kk + a_c0;
            af[mt][0] = __float_as_uint(As[r0 * 36 + c0]);
            af[mt][1] = __float_as_uint(As[(r0 + 8) * 36 + c0]);
            af[mt][2] = __float_as_uint(As[r0 * 36 + c0 + 4]);
            af[mt][3] = __float_as_uint(As[(r0 + 8) * 36 + c0 + 4]);
        }
#pragma unroll
        for (int nt = 0; nt < 7; ++nt) {
            int n = b_n0b + nt * 8;
            int k = kk + b_k0;
            bf[nt][0] = __float_as_uint(Ws[n * 36 + k]);
            bf[nt][1] = __float_as_uint(Ws[n * 36 + k + 4]);
        }
    };

    load_tile(0, 0);
    load_tile(1, 1);

    for (int kt = 0; kt < NKT; ++kt) {
        asm volatile("cp.async.wait_group 1;");
        __syncthreads();
        if (kt + 2 < NKT) load_tile(kt + 2, (kt + 2) % 3);
        else asm volatile("cp.async.commit_group;");

        const float* As = sm + (kt % 3) * STAGE_F;
        const float* Ws = As + 4608;

        uint32_t af[2][4][4];
        uint32_t bf[2][7][2];
        loadfrag(As, Ws, 0, af[0], bf[0]);
#pragma unroll
        for (int kki = 0; kki < 4; ++kki) {
            const int cur = kki & 1;
            if (kki < 3) loadfrag(As, Ws, (kki + 1) * 8, af[cur ^ 1], bf[cur ^ 1]);
#pragma unroll
            for (int mt = 0; mt < 4; ++mt)
#pragma unroll
                for (int nt = 0; nt < 7; ++nt)
                    mma_tf32(acc[mt][nt][0], acc[mt][nt][1], acc[mt][nt][2], acc[mt][nt][3],
                             af[cur][mt][0], af[cur][mt][1], af[cur][mt][2], af[cur][mt][3],
                             bf[cur][nt][0], bf[cur][nt][1]);
        }
    }
    __syncthreads();

    // ---- fused epilogue: relu(c + bias) overlap-added into c2t ----
#pragma unroll
    for (int nt = 0; nt < 7; ++nt) {
#pragma unroll
        for (int e = 0; e < 2; ++e) {
            int col = (int)n0 + wn * 56 + nt * 8 + 2 * (lane & 3) + e;
            int ch = col / (CK * P_);
            int rem = col - ch * (CK * P_);
            int k = rem / P_;
            int t = rem - k * P_ - k;                  // p - k
            if (t >= 0 && t < L_) {
                float bv = bias[col];
                float* base = d_c2t + t * BCH + ch;
#pragma unroll
                for (int mt = 0; mt < 4; ++mt) {
                    int row = wm * 64 + mt * 16 + (lane >> 2);
                    float v0 = fmaxf(acc[mt][nt][e] + bv, 0.f);
                    float v1 = fmaxf(acc[mt][nt][e + 2] + bv, 0.f);
                    atomicAdd(base + row * HIDC, v0);
                    atomicAdd(base + (row + 8) * HIDC, v1);
                }
            }
        }
    }
}

// ---------------- k2: gi = c2t @ Wih^T + bih on tensor cores ----------------
__global__ void __launch_bounds__(256, 1) k_gi(const float* __restrict__ Wih,
                                               const float* __restrict__ bih) {
    extern __shared__ float sm[];           // A 128x36 | B 320x36
    float* Bs = sm + 128 * 36;
    const int t = blockIdx.x;
    const int tid = threadIdx.x;
    const int lane = tid & 31, warp = tid >> 5;
    const int wm = warp >> 2, wn = warp & 3;
    uint32_t smbase = (uint32_t)__cvta_generic_to_shared(sm);

    if (tid < 180) {
        int r = 300 + tid / 9, c = (tid % 9) * 4;
        *(float4*)(Bs + r * 36 + c) = make_float4(0.f, 0.f, 0.f, 0.f);
    }
    {
        const float* a = d_c2t + (size_t)t * BCH;
#pragma unroll
        for (int i = 0; i < 4; i++) {
            int c = tid + i * 256;
            int row = c >> 3, kq = c & 7;
            asm volatile("cp.async.ca.shared.global [%0],[%1],16;" ::
                         "r"(smbase + (uint32_t)(row * 36 + kq * 4) * 4),
                         "l"(a + row * HIDC + kq * 4));
        }
    }
    {
        uint32_t bb = smbase + 128 * 36 * 4;
        for (int c = tid; c < 300 * 8; c += 256) {
            int row = c >> 3, kq = c & 7;
            asm volatile("cp.async.ca.shared.global [%0],[%1],16;" ::
                         "r"(bb + (uint32_t)(row * 36 + kq * 4) * 4),
                         "l"(Wih + row * HIDC + kq * 4));
        }
    }
    asm volatile("cp.async.commit_group;");
    asm volatile("cp.async.wait_group 0;");
    __syncthreads();

    float acc[4][10][4];
#pragma unroll
    for (int i = 0; i < 4; i++)
#pragma unroll
        for (int jj = 0; jj < 10; jj++)
#pragma unroll
            for (int r = 0; r < 4; r++) acc[i][jj][r] = 0.f;

#pragma unroll
    for (int kk = 0; kk < 32; kk += 8) {
        uint32_t af[4][4];
        uint32_t bf[10][2];
#pragma unroll
        for (int mt = 0; mt < 4; ++mt) {
            int r0 = wm * 64 + mt * 16 + (lane >> 2);
            int c0 = kk + (lane & 3);
            af[mt][0] = __float_as_uint(sm[r0 * 36 + c0]);
            af[mt][1] = __float_as_uint(sm[(r0 + 8) * 36 + c0]);
            af[mt][2] = __float_as_uint(sm[r0 * 36 + c0 + 4]);
            af[mt][3] = __float_as_uint(sm[(r0 + 8) * 36 + c0 + 4]);
        }
#pragma unroll
        for (int nt = 0; nt < 10; ++nt) {
            int n = wn * 80 + nt * 8 + (lane >> 2);
            int k = kk + (lane & 3);
            bf[nt][0] = __float_as_uint(Bs[n * 36 + k]);
            bf[nt][1] = __float_as_uint(Bs[n * 36 + k + 4]);
        }
#pragma unroll
        for (int mt = 0; mt < 4; ++mt)
#pragma unroll
            for (int nt = 0; nt < 10; ++nt)
                mma_tf32(acc[mt][nt][0], acc[mt][nt][1], acc[mt][nt][2], acc[mt][nt][3],
                         af[mt][0], af[mt][1], af[mt][2], af[mt][3],
                         bf[nt][0], bf[nt][1]);
    }

#pragma unroll
    for (int nt = 0; nt < 10; ++nt) {
        int j = wn * 80 + nt * 8 + 2 * (lane & 3);
        if (j < 300) {
            float b0 = bih[j], b1 = bih[j + 1];
#pragma unroll
            for (int mt = 0; mt < 4; ++mt) {
                int b = wm * 64 + mt * 16 + (lane >> 2);
                float2 v0 = {acc[mt][nt][0] + b0, acc[mt][nt][1] + b1};
                float2 v1 = {acc[mt][nt][2] + b0, acc[mt][nt][3] + b1};
                *(float2*)(d_gi + ((size_t)b * L_ + t) * GIP + j) = v0;
                *(float2*)(d_gi + ((size_t)(b + 8) * L_ + t) * GIP + j) = v1;
            }
        }
    }
}

// ---------------- k3: GRU1 (blocks 0..127) + skip GRU (blocks 128..143) ----
// Gate-triplet layout: warp w owns units [10w,10w+10); lane 3i+g holds gate g
// of unit 10w+i. ONE barrier per step, placed AFTER cp.async.wait_group so the
// completed gi prefetch is published to ALL warps (the round-15 bug: wait_group
// only orders the issuing thread's own groups). Per step:
//   wait(gi[t]) -> barrier -> issue gi[t+1] -> gate dot -> shfl -> act -> h write.
// Every buffer-reuse hazard (hbuf and gi_sh, both distance-2 double-buffered)
// has >=1 barrier between conflicting accesses.
__global__ void __launch_bounds__(320, 1) k_gru(
    const float* __restrict__ g1Whh, const float* __restrict__ g1bhh,
    const float* __restrict__ gsWih, const float* __restrict__ gsWhh,
    const float* __restrict__ gsbih, const float* __restrict__ gsbhh) {
    __shared__ __align__(16) float hbuf[2][104];
    __shared__ __align__(16) float gi_sh[2][GIP];
    __shared__ __align__(16) float ws[592];      // skip-GRU weight pool
    const int bid = blockIdx.x;
    const int j = threadIdx.x;

    if (bid < B_) {
        const int lane = j & 31, w = j >> 5;
        int i3 = lane / 3; if (i3 > 9) i3 = 9;
        int g = lane - 3 * i3; if (g > 2) g = 2;
        const int u = w * 10 + i3;                 // hidden unit [0,100)
        const int row = g * 100 + u;               // gate row [0,300)
        const bool writer = (lane < 30) && (g == 0);

        uint32_t gb = (uint32_t)__cvta_generic_to_shared(gi_sh);
        const float* gsrc = d_gi + (size_t)bid * L_ * GIP;

        // prologue: issue prefetch of gi[0] into buf 0
        if (j < 76)
            asm volatile("cp.async.ca.shared.global [%0],[%1],16;" ::
                         "r"(gb + (uint32_t)j * 16), "l"(gsrc + j * 4));
        asm volatile("cp.async.commit_group;");

        // gate-row weights register-resident
        ull whh2[50];
        {
            const ulonglong2* pw = (const ulonglong2*)(g1Whh + row * HIDR);
#pragma unroll
            for (int q = 0; q < 25; q++) { ulonglong2 v = pw[q]; whh2[2*q] = v.x; whh2[2*q+1] = v.y; }
        }
        const float bhh_r = g1bhh[row];
        if (j < 104) hbuf[0][j] = 0.f;
        float h_reg = 0.f;

        for (int t = 0; t < L_; ++t) {
            // wait for gi[t] prefetch (issuing threads), then publish to all
            asm volatile("cp.async.wait_group 0;");
            __syncthreads();
            // issue prefetch of gi[t+1] into the other buffer
            if (t + 1 < L_) {
                if (j < 76)
                    asm volatile("cp.async.ca.shared.global [%0],[%1],16;" ::
                                 "r"(gb + (uint32_t)(((t + 1) & 1) * GIP + j * 4) * 4),
                                 "l"(gsrc + (size_t)(t + 1) * GIP + j * 4));
                asm volatile("cp.async.commit_group;");
            }
            // gate dot: s = bhh_row + Whh_row . h   (4 accumulators)
            const ulonglong2* h2 = (const ulonglong2*)hbuf[t & 1];
            ull a0 = pk2(bhh_r, 0.f), a1 = pk2(0.f, 0.f);
            ull a2 = pk2(0.f, 0.f),  a3 = pk2(0.f, 0.f);
#pragma unroll
            for (int q = 0; q < 25; q++) {
                ulonglong2 hv = h2[q];
                if (q & 1) {
                    a2 = fma2_(hv.x, whh2[2*q], a2);
                    a3 = fma2_(hv.y, whh2[2*q+1], a3);
                } else {
                    a0 = fma2_(hv.x, whh2[2*q], a0);
                    a1 = fma2_(hv.y, whh2[2*q+1], a1);
                }
            }
            float l0, h0, l1, h1, l2, h2f, l3, h3;
            unpk2(a0, l0, h0); unpk2(a1, l1, h1);
            unpk2(a2, l2, h2f); unpk2(a3, l3, h3);
            float s = ((l0 + h0) + (l1 + h1)) + ((l2 + h2f) + (l3 + h3));

            // gather triplet within warp
            float sr = __shfl_sync(0xffffffffu, s, 3 * i3);
            float sz = __shfl_sync(0xffffffffu, s, 3 * i3 + 1);
            float sn = __shfl_sync(0xffffffffu, s, 3 * i3 + 2);

            const float* gi = gi_sh[t & 1];
            float r = sigm_a(gi[u] + sr);
            float z = sigm_a(gi[u + 100] + sz);
            float n = tanh_ap(gi[u + 200] + r * sn);
            h_reg = z * (h_reg - n) + n;
            if (writer) hbuf[(t + 1) & 1][u] = h_reg;
        }
        if (writer) d_h1[bid * HIDR + u] = h_reg;
    } else {
        for (int i = j; i < 480; i += 320) ws[i] = gsWih[i];
        for (int i = j; i < 75; i += 320) ws[480 + i] = gsWhh[i];
        if (j < 15) { ws[555 + j] = gsbih[j]; ws[570 + j] = gsbhh[j]; }
        __syncthreads();
        if (j < 192) {
            int seq = (bid - B_) * 192 + j;        // = b*SKIP + sk
            int b = seq / SKIP, sk = seq % SKIP;
            float h[5] = {0.f, 0.f, 0.f, 0.f, 0.f};
            for (int pt = 0; pt < PT; ++pt) {
                const float4* xp = (const float4*)(d_c2t + (size_t)(L_ - PT * SKIP + pt * SKIP + sk) * BCH + b * HIDC);
                float xv[32];
#pragma unroll
                for (int q = 0; q < 8; ++q) {
                    float4 v = xp[q];
                    xv[4*q] = v.x; xv[4*q+1] = v.y; xv[4*q+2] = v.z; xv[4*q+3] = v.w;
                }
                float gi[15], gh[15];
#pragma unroll
                for (int g2 = 0; g2 < 15; ++g2) {
                    float a = ws[555 + g2];
#pragma unroll
                    for (int i2 = 0; i2 < 32; ++i2) a += xv[i2] * ws[g2 * 32 + i2];
                    gi[g2] = a;
                    float bg = ws[570 + g2];
#pragma unroll
                    for (int i2 = 0; i2 < 5; ++i2) bg += h[i2] * ws[480 + g2 * 5 + i2];
                    gh[g2] = bg;
                }
#pragma unroll
                for (int q = 0; q < 5; ++q) {
                    float r = sigm_a(gi[q] + gh[q]);
                    float z = sigm_a(gi[5 + q] + gh[5 + q]);
                    float n = tanh_ap(gi[10 + q] + r * gh[10 + q]);
                    h[q] = z * (h[q] - n) + n;
                }
            }
#pragma unroll
            for (int q = 0; q < 5; ++q) d_hs[seq * 5 + q] = h[q];
        }
    }
}

// ---------------- k4: final linear + highway + sigmoid; warp per output ----
__global__ void __launch_bounds__(768) k_fin(const float* __restrict__ x,
                      const float* __restrict__ lw, const float* __restrict__ lb,
                      const float* __restrict__ hww, const float* __restrict__ hwb,
                      float* __restrict__ out) {
    int b = blockIdx.x;
    int m = threadIdx.x >> 5, lane = threadIdx.x & 31;
    const float* w = lw + m * (HIDR + SKIP * HIDS);
    float a = 0.f;
#pragma unroll
    for (int q = 0; q < 8; ++q) {
        int i = lane + 32 * q;
        if (i < HIDR) a += w[i] * d_h1[b * HIDR + i];
        else if (i < 220) a += w[i] * d_hs[b * 120 + i - 100];
        else if (i < 244) a += hww[i - 220] * x[b * KDIM + (P_ - HW_ + i - 220) * M_ + m];
    }
#pragma unroll
    for (int off = 16; off > 0; off >>= 1)
        a += __shfl_xor_sync(0xffffffffu, a, off);
    if (lane == 0)
        out[b * M_ + m] = 1.f / (1.f + __expf(-(a + lb[m] + hwb[0])));
}

// ---------------- launch ----------------
extern "C" void kernel_launch(void* const* d_in, const int* in_sizes, int n_in,
                              void* d_out, int out_size) {
    const float* x       = (const float*)d_in[0];
    const float* conv_w  = (const float*)d_in[1];
    const float* conv_b  = (const float*)d_in[2];
    const float* g1Wih   = (const float*)d_in[3];
    const float* g1Whh   = (const float*)d_in[4];
    const float* g1bih   = (const float*)d_in[5];
    const float* g1bhh   = (const float*)d_in[6];
    const float* gsWih   = (const float*)d_in[7];
    const float* gsWhh   = (const float*)d_in[8];
    const float* gsbih   = (const float*)d_in[9];
    const float* gsbhh   = (const float*)d_in[10];
    const float* lin1_w  = (const float*)d_in[11];
    const float* lin1_b  = (const float*)d_in[12];
    const float* hw_w    = (const float*)d_in[13];
    const float* hw_b    = (const float*)d_in[14];
    float* out = (float*)d_out;

    cudaFuncSetAttribute(k_gemm, cudaFuncAttributeMaxDynamicSharedMemorySize, 3 * STAGE_F * 4);
    cudaFuncSetAttribute(k_gi, cudaFuncAttributeMaxDynamicSharedMemorySize, (128 + 320) * 36 * 4);

    k_zero<<<(L_ * BCH / 4 + 255) / 256, 256>>>();
    k_gemm<<<NDIM / BN_, 256, 3 * STAGE_F * 4>>>(x, conv_w, conv_b);
    k_gi<<<L_, 256, (128 + 320) * 36 * 4>>>(g1Wih, g1bih);
    k_gru<<<B_ + 16, 320>>>(g1Whh, g1bhh, gsWih, gsWhh, gsbih, gsbhh);
    k_fin<<<B_, 768>>>(x, lin1_w, lin1_b, hw_w, hw_b, out);
}

// round 17
// speedup vs baseline: 1.0432x; 1.0421x over previous
#include <cuda_runtime.h>
#include <cstdint>

#define B_   128
#define P_   168
#define HIDC 32
#define CK   6
#define L_   163          // P - CK + 1
#define HIDR 100
#define HIDS 5
#define SKIP 24
#define PT   6
#define KDIM 4032         // P * 24
#define NDIM 32256        // P * HIDC * CK
#define HW_  24
#define M_   24
#define BCH  4096         // B_ * HIDC
#define GIP  304          // padded gi row

#define BN_     224       // GEMM N tile: 144 CTAs exactly
#define STAGE_F 12672     // (128+224)*36 floats per stage
#define NKT     126       // KDIM / 32

typedef unsigned long long ull;

// ---------------- scratch (device globals; no allocation) ----------------
__device__ float d_c[B_ * NDIM];           // conv output (post-relu)
__device__ float d_c2t[L_ * BCH];          // overlap-added, t-major [t][b][ch]
__device__ float d_gi[B_ * L_ * GIP];      // precomputed input projections
__device__ float d_h1[B_ * HIDR];
__device__ float d_hs[B_ * SKIP * HIDS];

// ---------------- helpers ----------------
__device__ __forceinline__ void mma_tf32(float& c0, float& c1, float& c2, float& c3,
                                         uint32_t a0, uint32_t a1, uint32_t a2, uint32_t a3,
                                         uint32_t b0, uint32_t b1) {
    asm volatile(
        "mma.sync.aligned.m16n8k8.row.col.f32.tf32.tf32.f32 "
        "{%0,%1,%2,%3},{%4,%5,%6,%7},{%8,%9},{%0,%1,%2,%3};"
        : "+f"(c0), "+f"(c1), "+f"(c2), "+f"(c3)
        : "r"(a0), "r"(a1), "r"(a2), "r"(a3), "r"(b0), "r"(b1));
}
__device__ __forceinline__ ull pk2(float lo, float hi) {
    ull r; asm("mov.b64 %0,{%1,%2};" : "=l"(r) : "f"(lo), "f"(hi)); return r;
}
__device__ __forceinline__ void unpk2(ull v, float& lo, float& hi) {
    asm("mov.b64 {%0,%1},%2;" : "=f"(lo), "=f"(hi) : "l"(v));
}
__device__ __forceinline__ ull fma2_(ull a, ull b, ull c) {
    ull d; asm("fma.rn.f32x2 %0,%1,%2,%3;" : "=l"(d) : "l"(a), "l"(b), "l"(c));
    return d;
}
__device__ __forceinline__ float tanh_ap(float x) {
    float y; asm("tanh.approx.f32 %0,%1;" : "=f"(y) : "f"(x)); return y;
}
__device__ __forceinline__ float sigm_a(float x) {
    return 0.5f * tanh_ap(0.5f * x) + 0.5f;
}

// ---------------- k1: GEMM c = relu(x @ W^T + b), tf32 (round-6 proven) ------
__global__ void __launch_bounds__(256, 1) k_gemm(const float* __restrict__ x,
                                                 const float* __restrict__ W,
                                                 const float* __restrict__ bias) {
    extern __shared__ float sm[];
    const int tid = threadIdx.x;
    const long n0 = (long)blockIdx.x * BN_;
    const int lane = tid & 31, warp = tid >> 5;
    const int wm = warp >> 2, wn = warp & 3;
    uint32_t smbase = (uint32_t)__cvta_generic_to_shared(sm);
    const float* gW = W + n0 * KDIM;

    float acc[4][7][4];
#pragma unroll
    for (int i = 0; i < 4; i++)
#pragma unroll
        for (int jj = 0; jj < 7; jj++)
#pragma unroll
            for (int r = 0; r < 4; r++) acc[i][jj][r] = 0.f;

    auto load_tile = [&](int kt, int s) {
        const float* a = x + kt * 32;
        const float* w = gW + kt * 32;
        uint32_t sb = smbase + s * STAGE_F * 4;
#pragma unroll
        for (int i = 0; i < 4; i++) {
            int c = tid + i * 256;
            int row = c >> 3, kq = c & 7;
            asm volatile("cp.async.ca.shared.global [%0],[%1],16;" ::
                         "r"(sb + (row * 36 + kq * 4) * 4),
                         "l"(a + (long)row * KDIM + kq * 4));
        }
#pragma unroll
        for (int i = 0; i < 7; i++) {
            int c = tid + i * 256;
            int n = c >> 3, kq = c & 7;
            asm volatile("cp.async.ca.shared.global [%0],[%1],16;" ::
                         "r"(sb + (4608 + n * 36 + kq * 4) * 4),
                         "l"(w + (long)n * KDIM + kq * 4));
        }
        asm volatile("cp.async.commit_group;");
    };

    load_tile(0, 0);
    load_tile(1, 1);

    for (int kt = 0; kt < NKT; ++kt) {
        asm volatile("cp.async.wait_group 1;");
        __syncthreads();
        const float* As = sm + (kt % 3) * STAGE_F;
        const float* Ws = As + 4608;
#pragma unroll
        for (int kk = 0; kk < 32; kk += 8) {
            uint32_t af[4][4];
            uint32_t bf[7][2];
#pragma unroll
            for (int mt = 0; mt < 4; ++mt) {
                int r0 = wm * 64 + mt * 16 + (lane >> 2);
                int c0 = kk + (lane & 3);
                af[mt][0] = __float_as_uint(As[r0 * 36 + c0]);
                af[mt][1] = __float_as_uint(As[(r0 + 8) * 36 + c0]);
                af[mt][2] = __float_as_uint(As[r0 * 36 + c0 + 4]);
                af[mt][3] = __float_as_uint(As[(r0 + 8) * 36 + c0 + 4]);
            }
#pragma unroll
            for (int nt = 0; nt < 7; ++nt) {
                int n = wn * 56 + nt * 8 + (lane >> 2);
                int k = kk + (lane & 3);
                bf[nt][0] = __float_as_uint(Ws[n * 36 + k]);
                bf[nt][1] = __float_as_uint(Ws[n * 36 + k + 4]);
            }
#pragma unroll
            for (int mt = 0; mt < 4; ++mt)
#pragma unroll
                for (int nt = 0; nt < 7; ++nt)
                    mma_tf32(acc[mt][nt][0], acc[mt][nt][1], acc[mt][nt][2], acc[mt][nt][3],
                             af[mt][0], af[mt][1], af[mt][2], af[mt][3],
                             bf[nt][0], bf[nt][1]);
        }
        __syncthreads();
        if (kt + 2 < NKT) load_tile(kt + 2, (kt + 2) % 3);
        else asm volatile("cp.async.commit_group;");
    }

#pragma unroll
    for (int mt = 0; mt < 4; ++mt) {
        int row = wm * 64 + mt * 16 + (lane >> 2);
#pragma unroll
        for (int nt = 0; nt < 7; ++nt) {
            long col = n0 + wn * 56 + nt * 8 + 2 * (lane & 3);
            float b0 = bias[col], b1 = bias[col + 1];
            float2 v0 = {fmaxf(acc[mt][nt][0] + b0, 0.f), fmaxf(acc[mt][nt][1] + b1, 0.f)};
            float2 v1 = {fmaxf(acc[mt][nt][2] + b0, 0.f), fmaxf(acc[mt][nt][3] + b1, 0.f)};
            *(float2*)&d_c[(long)row * NDIM + col] = v0;
            *(float2*)&d_c[(long)(row + 8) * NDIM + col] = v1;
        }
    }
}

// ---------------- k2: overlap-add to t-major c2t (round-6 proven) ----------
__global__ void k_overlap() {
    int bc = blockIdx.x;           // b*32 + ch
    int b = bc >> 5, ch = bc & 31;
    int t = threadIdx.x;
    if (t >= L_) return;
    const float* cb = d_c + (long)b * NDIM + ch * (CK * P_);
    float s = 0.f;
#pragma unroll
    for (int k = 0; k < CK; k++) s += cb[k * (P_ + 1) + t];
    d_c2t[t * BCH + bc] = s;
}

// ---------------- k2b: gi = c2t @ Wih^T + bih on tensor cores (round-13) ----
__global__ void __launch_bounds__(256, 1) k_gi(const float* __restrict__ Wih,
                                               const float* __restrict__ bih) {
    extern __shared__ float sm[];           // A 128x36 | B 320x36
    float* Bs = sm + 128 * 36;
    const int t = blockIdx.x;
    const int tid = threadIdx.x;
    const int lane = tid & 31, warp = tid >> 5;
    const int wm = warp >> 2, wn = warp & 3;
    uint32_t smbase = (uint32_t)__cvta_generic_to_shared(sm);

    if (tid < 180) {
        int r = 300 + tid / 9, c = (tid % 9) * 4;
        *(float4*)(Bs + r * 36 + c) = make_float4(0.f, 0.f, 0.f, 0.f);
    }
    {
        const float* a = d_c2t + (size_t)t * BCH;
#pragma unroll
        for (int i = 0; i < 4; i++) {
            int c = tid + i * 256;
            int row = c >> 3, kq = c & 7;
            asm volatile("cp.async.ca.shared.global [%0],[%1],16;" ::
                         "r"(smbase + (uint32_t)(row * 36 + kq * 4) * 4),
                         "l"(a + row * HIDC + kq * 4));
        }
    }
    {
        uint32_t bb = smbase + 128 * 36 * 4;
        for (int c = tid; c < 300 * 8; c += 256) {
            int row = c >> 3, kq = c & 7;
            asm volatile("cp.async.ca.shared.global [%0],[%1],16;" ::
                         "r"(bb + (uint32_t)(row * 36 + kq * 4) * 4),
                         "l"(Wih + row * HIDC + kq * 4));
        }
    }
    asm volatile("cp.async.commit_group;");
    asm volatile("cp.async.wait_group 0;");
    __syncthreads();

    float acc[4][10][4];
#pragma unroll
    for (int i = 0; i < 4; i++)
#pragma unroll
        for (int jj = 0; jj < 10; jj++)
#pragma unroll
            for (int r = 0; r < 4; r++) acc[i][jj][r] = 0.f;

#pragma unroll
    for (int kk = 0; kk < 32; kk += 8) {
        uint32_t af[4][4];
        uint32_t bf[10][2];
#pragma unroll
        for (int mt = 0; mt < 4; ++mt) {
            int r0 = wm * 64 + mt * 16 + (lane >> 2);
            int c0 = kk + (lane & 3);
            af[mt][0] = __float_as_uint(sm[r0 * 36 + c0]);
            af[mt][1] = __float_as_uint(sm[(r0 + 8) * 36 + c0]);
            af[mt][2] = __float_as_uint(sm[r0 * 36 + c0 + 4]);
            af[mt][3] = __float_as_uint(sm[(r0 + 8) * 36 + c0 + 4]);
        }
#pragma unroll
        for (int nt = 0; nt < 10; ++nt) {
            int n = wn * 80 + nt * 8 + (lane >> 2);
            int k = kk + (lane & 3);
            bf[nt][0] = __float_as_uint(Bs[n * 36 + k]);
            bf[nt][1] = __float_as_uint(Bs[n * 36 + k + 4]);
        }
#pragma unroll
        for (int mt = 0; mt < 4; ++mt)
#pragma unroll
            for (int nt = 0; nt < 10; ++nt)
                mma_tf32(acc[mt][nt][0], acc[mt][nt][1], acc[mt][nt][2], acc[mt][nt][3],
                         af[mt][0], af[mt][1], af[mt][2], af[mt][3],
                         bf[nt][0], bf[nt][1]);
    }

#pragma unroll
    for (int nt = 0; nt < 10; ++nt) {
        int j = wn * 80 + nt * 8 + 2 * (lane & 3);
        if (j < 300) {
            float b0 = bih[j], b1 = bih[j + 1];
#pragma unroll
            for (int mt = 0; mt < 4; ++mt) {
                int b = wm * 64 + mt * 16 + (lane >> 2);
                float2 v0 = {acc[mt][nt][0] + b0, acc[mt][nt][1] + b1};
                float2 v1 = {acc[mt][nt][2] + b0, acc[mt][nt][3] + b1};
                *(float2*)(d_gi + ((size_t)b * L_ + t) * GIP + j) = v0;
                *(float2*)(d_gi + ((size_t)(b + 8) * L_ + t) * GIP + j) = v1;
            }
        }
    }
}

// ---------------- k3: GRU1 (blocks 0..127) + skip GRU (round-13/14 proven) --
__global__ void __launch_bounds__(320, 1) k_gru(
    const float* __restrict__ g1Whh, const float* __restrict__ g1bhh,
    const float* __restrict__ gsWih, const float* __restrict__ gsWhh,
    const float* __restrict__ gsbih, const float* __restrict__ gsbhh) {
    __shared__ __align__(16) float h_sh[104];
    __shared__ __align__(16) float s_sh[304];
    __shared__ __align__(16) float gi_sh[2][GIP];
    __shared__ __align__(16) float ws[592];      // skip-GRU weight pool
    const int bid = blockIdx.x;
    const int j = threadIdx.x;

    if (bid < B_) {
        uint32_t gb = (uint32_t)__cvta_generic_to_shared(gi_sh);
        const float* gsrc = d_gi + (size_t)bid * L_ * GIP;

        if (j < 76)
            asm volatile("cp.async.ca.shared.global [%0],[%1],16;" ::
                         "r"(gb + (uint32_t)j * 16), "l"(gsrc + j * 4));
        asm volatile("cp.async.commit_group;");

        ull whh2[50];
        float bhh_j = 0.f;
        if (j < 300) {
            const ulonglong2* pw = (const ulonglong2*)(g1Whh + j * HIDR);
#pragma unroll
            for (int q = 0; q < 25; q++) { ulonglong2 v = pw[q]; whh2[2*q] = v.x; whh2[2*q+1] = v.y; }
            bhh_j = g1bhh[j];
        }
        if (j < 104) h_sh[j] = 0.f;
        float h_reg = 0.f;
        asm volatile("cp.async.wait_group 0;");
        __syncthreads();

        for (int t = 0; t < L_; ++t) {
            if (t + 1 < L_) {
                if (j < 76)
                    asm volatile("cp.async.ca.shared.global [%0],[%1],16;" ::
                                 "r"(gb + (uint32_t)(((t + 1) & 1) * GIP + j * 4) * 4),
                                 "l"(gsrc + (size_t)(t + 1) * GIP + j * 4));
                asm volatile("cp.async.commit_group;");
            }
            if (j < 300) {
                const ulonglong2* h2 = (const ulonglong2*)h_sh;
                ull a0 = pk2(bhh_j, 0.f), a1 = pk2(0.f, 0.f);
                ull a2 = pk2(0.f, 0.f),  a3 = pk2(0.f, 0.f);
#pragma unroll
                for (int q = 0; q < 25; q++) {
                    ulonglong2 hv = h2[q];
                    if (q & 1) {
                        a2 = fma2_(hv.x, whh2[2*q], a2);
                        a3 = fma2_(hv.y, whh2[2*q+1], a3);
                    } else {
                        a0 = fma2_(hv.x, whh2[2*q], a0);
                        a1 = fma2_(hv.y, whh2[2*q+1], a1);
                    }
                }
                float l0, h0, l1, h1, l2, h2f, l3, h3;
                unpk2(a0, l0, h0); unpk2(a1, l1, h1);
                unpk2(a2, l2, h2f); unpk2(a3, l3, h3);
                s_sh[j] = ((l0 + h0) + (l1 + h1)) + ((l2 + h2f) + (l3 + h3));
            }
            if (t + 1 < L_) asm volatile("cp.async.wait_group 1;");
            else            asm volatile("cp.async.wait_group 0;");
            __syncthreads();
            if (j < HIDR) {
                const float* gi = gi_sh[t & 1];
                float r = sigm_a(gi[j] + s_sh[j]);
                float z = sigm_a(gi[j + 100] + s_sh[j + 100]);
                float n = tanh_ap(gi[j + 200] + r * s_sh[j + 200]);
                h_reg = z * (h_reg - n) + n;
                h_sh[j] = h_reg;
            }
            __syncthreads();
        }
        if (j < HIDR) d_h1[bid * HIDR + j] = h_reg;
    } else {
        for (int i = j; i < 480; i += 320) ws[i] = gsWih[i];
        for (int i = j; i < 75; i += 320) ws[480 + i] = gsWhh[i];
        if (j < 15) { ws[555 + j] = gsbih[j]; ws[570 + j] = gsbhh[j]; }
        __syncthreads();
        if (j < 192) {
            int seq = (bid - B_) * 192 + j;        // = b*SKIP + sk
            int b = seq / SKIP, sk = seq % SKIP;
            float h[5] = {0.f, 0.f, 0.f, 0.f, 0.f};
            for (int pt = 0; pt < PT; ++pt) {
                const float4* xp = (const float4*)(d_c2t + (size_t)(L_ - PT * SKIP + pt * SKIP + sk) * BCH + b * HIDC);
                float xv[32];
#pragma unroll
                for (int q = 0; q < 8; ++q) {
                    float4 v = xp[q];
                    xv[4*q] = v.x; xv[4*q+1] = v.y; xv[4*q+2] = v.z; xv[4*q+3] = v.w;
                }
                float gi[15], gh[15];
#pragma unroll
                for (int g2 = 0; g2 < 15; ++g2) {
                    float a = ws[555 + g2];
#pragma unroll
                    for (int i2 = 0; i2 < 32; ++i2) a += xv[i2] * ws[g2 * 32 + i2];
                    gi[g2] = a;
                    float bg = ws[570 + g2];
#pragma unroll
                    for (int i2 = 0; i2 < 5; ++i2) bg += h[i2] * ws[480 + g2 * 5 + i2];
                    gh[g2] = bg;
                }
#pragma unroll
                for (int q = 0; q < 5; ++q) {
                    float r = sigm_a(gi[q] + gh[q]);
                    float z = sigm_a(gi[5 + q] + gh[5 + q]);
                    float n = tanh_ap(gi[10 + q] + r * gh[10 + q]);
                    h[q] = z * (h[q] - n) + n;
                }
            }
#pragma unroll
            for (int q = 0; q < 5; ++q) d_hs[seq * 5 + q] = h[q];
        }
    }
}

// ---------------- k4: final linear + highway + sigmoid; warp per output ----
__global__ void __launch_bounds__(768) k_fin(const float* __restrict__ x,
                      const float* __restrict__ lw, const float* __restrict__ lb,
                      const float* __restrict__ hww, const float* __restrict__ hwb,
                      float* __restrict__ out) {
    int b = blockIdx.x;
    int m = threadIdx.x >> 5, lane = threadIdx.x & 31;
    const float* w = lw + m * (HIDR + SKIP * HIDS);
    float a = 0.f;
#pragma unroll
    for (int q = 0; q < 8; ++q) {
        int i = lane + 32 * q;
        if (i < HIDR) a += w[i] * d_h1[b * HIDR + i];
        else if (i < 220) a += w[i] * d_hs[b * 120 + i - 100];
        else if (i < 244) a += hww[i - 220] * x[b * KDIM + (P_ - HW_ + i - 220) * M_ + m];
    }
#pragma unroll
    for (int off = 16; off > 0; off >>= 1)
        a += __shfl_xor_sync(0xffffffffu, a, off);
    if (lane == 0)
        out[b * M_ + m] = 1.f / (1.f + __expf(-(a + lb[m] + hwb[0])));
}

// ---------------- launch ----------------
extern "C" void kernel_launch(void* const* d_in, const int* in_sizes, int n_in,
                              void* d_out, int out_size) {
    const float* x       = (const float*)d_in[0];
    const float* conv_w  = (const float*)d_in[1];
    const float* conv_b  = (const float*)d_in[2];
    const float* g1Wih   = (const float*)d_in[3];
    const float* g1Whh   = (const float*)d_in[4];
    const float* g1bih   = (const float*)d_in[5];
    const float* g1bhh   = (const float*)d_in[6];
    const float* gsWih   = (const float*)d_in[7];
    const float* gsWhh   = (const float*)d_in[8];
    const float* gsbih   = (const float*)d_in[9];
    const float* gsbhh   = (const float*)d_in[10];
    const float* lin1_w  = (const float*)d_in[11];
    const float* lin1_b  = (const float*)d_in[12];
    const float* hw_w    = (const float*)d_in[13];
    const float* hw_b    = (const float*)d_in[14];
    float* out = (float*)d_out;

    cudaFuncSetAttribute(k_gemm, cudaFuncAttributeMaxDynamicSharedMemorySize, 3 * STAGE_F * 4);
    cudaFuncSetAttribute(k_gi, cudaFuncAttributeMaxDynamicSharedMemorySize, (128 + 320) * 36 * 4);

    k_gemm<<<NDIM / BN_, 256, 3 * STAGE_F * 4>>>(x, conv_w, conv_b);
    k_overlap<<<BCH, 192>>>();
    k_gi<<<L_, 256, (128 + 320) * 36 * 4>>>(g1Wih, g1bih);
    k_gru<<<B_ + 16, 320>>>(g1Whh, g1bhh, gsWih, gsWhh, gsbih, gsbhh);
    k_fin<<<B_, 768>>>(x, lin1_w, lin1_b, hw_w, hw_b, out);
}